// round 15
// baseline (speedup 1.0000x reference)
#include <cuda_runtime.h>
#include <cuda_fp16.h>
#include <math.h>

#define N_NODES 50000
#define N_EDGES 1600000
#define N_GRAPHS 2048
#define DIM 133
#define HPH 136          // padded halves per feature row (272 B, 16B aligned)
#define H2 68            // half2 per row
#define HU2 34           // uint2 (8B) per row
#define EPS 1e-5f
#define NB 196           // ceil(50000/256)
#define WSTRIDE 136
#define KSTEPS 17        // 17*8 = 136 >= 133
#define NTILES 17

// ---------------- scratch (device globals; no allocation allowed) ----------------
__device__ __align__(16) __half g_h[(size_t)N_NODES * HPH];  // GEMM output (fp16)
__device__ __align__(16) __half g_t[(size_t)N_NODES * HPH];  // layer output (fp16)
__device__ int    g_cnt[N_NODES];              // in-degree histogram (no self loop)
__device__ int    g_off[N_NODES];              // CSR row offsets
__device__ int    g_cursor[N_NODES];           // scatter cursors
__device__ int2   g_edge[N_EDGES];             // CSR: {src, bitcast(norm=dinv[s]*dinv[d])}
__device__ float  g_dinv[N_NODES];             // rsqrt(deg+1)
__device__ int    g_bsum[NB];                  // per-block histogram sums
__device__ int    g_goff[N_GRAPHS + 1];        // per-graph node ranges (batch sorted)
__device__ float  g_sc[2][HPH];                // BN scale  per layer
__device__ float  g_sh[2][HPH];                // BN shift  per layer

// ---------------- preprocessing ----------------
__global__ __launch_bounds__(256) void prep_kernel(const int* __restrict__ batch,
                                                   const float* __restrict__ g1,
                                                   const float* __restrict__ be1,
                                                   const float* __restrict__ rm1,
                                                   const float* __restrict__ rv1,
                                                   const float* __restrict__ g2,
                                                   const float* __restrict__ be2,
                                                   const float* __restrict__ rm2,
                                                   const float* __restrict__ rv2) {
    int i = blockIdx.x * blockDim.x + threadIdx.x;
    if (blockIdx.x == 0 && threadIdx.x < HPH) {
        int d = threadIdx.x;
        if (d < DIM) {
            float s1 = g1[d] * rsqrtf(rv1[d] + EPS);
            g_sc[0][d] = s1;
            g_sh[0][d] = be1[d] - rm1[d] * s1;
            float s2 = g2[d] * rsqrtf(rv2[d] + EPS);
            g_sc[1][d] = s2;
            g_sh[1][d] = be2[d] - rm2[d] * s2;
        } else {
            g_sc[0][d] = 0.f; g_sh[0][d] = 0.f;
            g_sc[1][d] = 0.f; g_sh[1][d] = 0.f;
        }
    }
    if (i >= N_NODES) return;
    g_cnt[i] = 0;
    int b = batch[i];
    int prev = (i == 0) ? -1 : batch[i - 1];
    for (int g = prev + 1; g <= b; g++) g_goff[g] = i;
    if (i == N_NODES - 1) {
        for (int g = b + 1; g <= N_GRAPHS; g++) g_goff[g] = N_NODES;
    }
}

__global__ void hist_kernel(const int* __restrict__ col) {
    for (int e = blockIdx.x * blockDim.x + threadIdx.x; e < N_EDGES;
         e += gridDim.x * blockDim.x) {
        atomicAdd(&g_cnt[col[e]], 1);
    }
}

__global__ __launch_bounds__(256) void reduce_kernel() {
    int i = blockIdx.x * 256 + threadIdx.x;
    int v = (i < N_NODES) ? g_cnt[i] : 0;
    #pragma unroll
    for (int off = 16; off > 0; off >>= 1)
        v += __shfl_down_sync(0xFFFFFFFFu, v, off);
    __shared__ int ws[8];
    int lane = threadIdx.x & 31, w = threadIdx.x >> 5;
    if (lane == 0) ws[w] = v;
    __syncthreads();
    if (threadIdx.x == 0) {
        int s = 0;
        #pragma unroll
        for (int j = 0; j < 8; j++) s += ws[j];
        g_bsum[blockIdx.x] = s;
    }
}

__global__ __launch_bounds__(256) void scan_apply_kernel() {
    int t = threadIdx.x;
    int lane = t & 31, w = t >> 5;

    int pv = (t < blockIdx.x) ? g_bsum[t] : 0;
    #pragma unroll
    for (int off = 16; off > 0; off >>= 1)
        pv += __shfl_down_sync(0xFFFFFFFFu, pv, off);
    __shared__ int wred[8];
    __shared__ int pref;
    if (lane == 0) wred[w] = pv;
    __syncthreads();
    if (t == 0) {
        int s = 0;
        #pragma unroll
        for (int j = 0; j < 8; j++) s += wred[j];
        pref = s;
    }

    int i = blockIdx.x * 256 + t;
    int v = (i < N_NODES) ? g_cnt[i] : 0;
    int s = v;
    #pragma unroll
    for (int d = 1; d < 32; d <<= 1) {
        int tt = __shfl_up_sync(0xFFFFFFFFu, s, d);
        if (lane >= d) s += tt;
    }
    __shared__ int ws[8];
    __shared__ int wo[8];
    if (lane == 31) ws[w] = s;
    __syncthreads();
    if (t == 0) {
        int r = 0;
        #pragma unroll
        for (int j = 0; j < 8; j++) { wo[j] = r; r += ws[j]; }
    }
    __syncthreads();
    if (i < N_NODES) {
        int excl = pref + wo[w] + (s - v);
        g_off[i] = excl;
        g_cursor[i] = excl;
        g_dinv[i] = rsqrtf((float)(v + 1));   // +1 self loop
    }
}

__global__ void scatter_kernel(const int* __restrict__ row,
                               const int* __restrict__ col) {
    for (int e = blockIdx.x * blockDim.x + threadIdx.x; e < N_EDGES;
         e += gridDim.x * blockDim.x) {
        int c = col[e];
        int r = row[e];
        int p = atomicAdd(&g_cursor[c], 1);
        float norm = g_dinv[r] * g_dinv[c];
        g_edge[p] = make_int2(r, __float_as_int(norm));
    }
}

// ---------- tf32 tensor-core GEMM (exact R10 structure: fragments from GMEM) ----------
__device__ __forceinline__ unsigned f2tf32(float f) {
    unsigned u;
    asm("cvt.rna.tf32.f32 %0, %1;" : "=r"(u) : "f"(f));
    return u;
}

__global__ __launch_bounds__(128) void gemm_tc_kernel(const float* __restrict__ A_ext,
                                                      const float* __restrict__ W,
                                                      int use_gt) {
    extern __shared__ unsigned Ws[];   // WSTRIDE * WSTRIDE tf32 words
    int tid = threadIdx.x;

    for (int idx = tid; idx < WSTRIDE * WSTRIDE; idx += 128) {
        int k = idx / WSTRIDE, n = idx - k * WSTRIDE;
        float v = (k < DIM && n < DIM) ? W[k * DIM + n] : 0.f;
        Ws[idx] = f2tf32(v);
    }
    __syncthreads();

    int warp = tid >> 5, lane = tid & 31;
    int gid = lane >> 2;    // 0..7
    int tig = lane & 3;     // 0..3
    int m0 = blockIdx.x * 64 + warp * 16;

    float acc[NTILES][4];
    #pragma unroll
    for (int n = 0; n < NTILES; n++) {
        acc[n][0] = acc[n][1] = acc[n][2] = acc[n][3] = 0.f;
    }

    int r0 = m0 + gid;
    int r1 = m0 + gid + 8;
    bool v0 = r0 < N_NODES, v1 = r1 < N_NODES;
    const float* Ar0 = A_ext + (size_t)r0 * DIM;
    const float* Ar1 = A_ext + (size_t)r1 * DIM;
    const __half* At0 = g_t + (size_t)r0 * HPH;
    const __half* At1 = g_t + (size_t)r1 * HPH;

    for (int ks = 0; ks < KSTEPS; ks++) {
        int k0 = ks * 8;
        int c0 = k0 + tig, c1 = k0 + tig + 4;
        float f0, f1, f2, f3;
        if (use_gt) {
            f0 = (v0 && c0 < DIM) ? __half2float(At0[c0]) : 0.f;
            f1 = (v1 && c0 < DIM) ? __half2float(At1[c0]) : 0.f;
            f2 = (v0 && c1 < DIM) ? __half2float(At0[c1]) : 0.f;
            f3 = (v1 && c1 < DIM) ? __half2float(At1[c1]) : 0.f;
        } else {
            f0 = (v0 && c0 < DIM) ? Ar0[c0] : 0.f;
            f1 = (v1 && c0 < DIM) ? Ar1[c0] : 0.f;
            f2 = (v0 && c1 < DIM) ? Ar0[c1] : 0.f;
            f3 = (v1 && c1 < DIM) ? Ar1[c1] : 0.f;
        }
        unsigned a0 = f2tf32(f0), a1 = f2tf32(f1), a2 = f2tf32(f2), a3 = f2tf32(f3);

        #pragma unroll
        for (int nt = 0; nt < NTILES; nt++) {
            unsigned b0 = Ws[(k0 + tig) * WSTRIDE + nt * 8 + gid];
            unsigned b1 = Ws[(k0 + tig + 4) * WSTRIDE + nt * 8 + gid];
            asm volatile(
                "mma.sync.aligned.m16n8k8.row.col.f32.tf32.tf32.f32 "
                "{%0,%1,%2,%3}, {%4,%5,%6,%7}, {%8,%9}, {%0,%1,%2,%3};"
                : "+f"(acc[nt][0]), "+f"(acc[nt][1]),
                  "+f"(acc[nt][2]), "+f"(acc[nt][3])
                : "r"(a0), "r"(a1), "r"(a2), "r"(a3), "r"(b0), "r"(b1));
        }
    }

    __half2* H2p = (__half2*)g_h;
    #pragma unroll
    for (int nt = 0; nt < NTILES; nt++) {
        int h2i = nt * 4 + tig;             // 0..67 (full row coverage)
        if (v0) H2p[(size_t)r0 * H2 + h2i] = __floats2half2_rn(acc[nt][0], acc[nt][1]);
        if (v1) H2p[(size_t)r1 * H2 + h2i] = __floats2half2_rn(acc[nt][2], acc[nt][3]);
    }
}

// -------- aggregation: g_t = BN(relu(scatter(norm * g_h[src]) + b)) -----------
// one warp per node; 1x LDG.64 (halves 0-127, lane d=4l..4l+3) + 3-lane tail
__global__ __launch_bounds__(256) void agg_kernel(const float* __restrict__ b,
                                                  int layer) {
    int node = (blockIdx.x * blockDim.x + threadIdx.x) >> 5;
    int lane = threadIdx.x & 31;
    if (node >= N_NODES) return;
    const uint2* __restrict__ h64 = (const uint2*)g_h;
    const __half2* __restrict__ h2 = (const __half2*)g_h;

    float di = g_dinv[node];
    int start = g_off[node];
    int end = (node + 1 < N_NODES) ? g_off[node + 1] : N_EDGES;

    bool tl = lane < 3;
    float sw = di * di;   // self-loop weight
    float4 am;            // main accum: d = 4*lane .. 4*lane+3
    float2 at = make_float2(0.f, 0.f);   // tail: d = 128+2*lane (lanes 0-2)
    {
        uint2 sv = h64[(size_t)node * HU2 + lane];
        float2 p = __half22float2(*(const __half2*)&sv.x);
        float2 q = __half22float2(*(const __half2*)&sv.y);
        am = make_float4(sw * p.x, sw * p.y, sw * q.x, sw * q.y);
        if (tl) {
            float2 r = __half22float2(h2[(size_t)node * H2 + 64 + lane]);
            at = make_float2(sw * r.x, sw * r.y);
        }
    }

    for (int j = start; j < end; j += 32) {
        int jj = j + lane;
        int2 e2 = (jj < end) ? g_edge[jj] : make_int2(0, 0);
        int cnt = min(32, end - j);
        int l = 0;
        for (; l + 4 <= cnt; l += 4) {
            int s0 = __shfl_sync(0xFFFFFFFFu, e2.x, l);
            int s1 = __shfl_sync(0xFFFFFFFFu, e2.x, l + 1);
            int s2 = __shfl_sync(0xFFFFFFFFu, e2.x, l + 2);
            int s3 = __shfl_sync(0xFFFFFFFFu, e2.x, l + 3);
            float w0 = __int_as_float(__shfl_sync(0xFFFFFFFFu, e2.y, l));
            float w1 = __int_as_float(__shfl_sync(0xFFFFFFFFu, e2.y, l + 1));
            float w2 = __int_as_float(__shfl_sync(0xFFFFFFFFu, e2.y, l + 2));
            float w3 = __int_as_float(__shfl_sync(0xFFFFFFFFu, e2.y, l + 3));
            // issue all loads first (2 per edge: 1 full-warp LDG.64 + 1 3-lane LDG.32)
            uint2 v0 = h64[(size_t)s0 * HU2 + lane];
            uint2 v1 = h64[(size_t)s1 * HU2 + lane];
            uint2 v2 = h64[(size_t)s2 * HU2 + lane];
            uint2 v3 = h64[(size_t)s3 * HU2 + lane];
            __half2 t0, t1, t2, t3;
            if (tl) {
                t0 = h2[(size_t)s0 * H2 + 64 + lane];
                t1 = h2[(size_t)s1 * H2 + 64 + lane];
                t2 = h2[(size_t)s2 * H2 + 64 + lane];
                t3 = h2[(size_t)s3 * H2 + 64 + lane];
            }
            float2 f, g;
            f = __half22float2(*(const __half2*)&v0.x);
            g = __half22float2(*(const __half2*)&v0.y);
            am.x = fmaf(w0, f.x, am.x); am.y = fmaf(w0, f.y, am.y);
            am.z = fmaf(w0, g.x, am.z); am.w = fmaf(w0, g.y, am.w);
            f = __half22float2(*(const __half2*)&v1.x);
            g = __half22float2(*(const __half2*)&v1.y);
            am.x = fmaf(w1, f.x, am.x); am.y = fmaf(w1, f.y, am.y);
            am.z = fmaf(w1, g.x, am.z); am.w = fmaf(w1, g.y, am.w);
            f = __half22float2(*(const __half2*)&v2.x);
            g = __half22float2(*(const __half2*)&v2.y);
            am.x = fmaf(w2, f.x, am.x); am.y = fmaf(w2, f.y, am.y);
            am.z = fmaf(w2, g.x, am.z); am.w = fmaf(w2, g.y, am.w);
            f = __half22float2(*(const __half2*)&v3.x);
            g = __half22float2(*(const __half2*)&v3.y);
            am.x = fmaf(w3, f.x, am.x); am.y = fmaf(w3, f.y, am.y);
            am.z = fmaf(w3, g.x, am.z); am.w = fmaf(w3, g.y, am.w);
            if (tl) {
                f = __half22float2(t0); at.x = fmaf(w0, f.x, at.x); at.y = fmaf(w0, f.y, at.y);
                f = __half22float2(t1); at.x = fmaf(w1, f.x, at.x); at.y = fmaf(w1, f.y, at.y);
                f = __half22float2(t2); at.x = fmaf(w2, f.x, at.x); at.y = fmaf(w2, f.y, at.y);
                f = __half22float2(t3); at.x = fmaf(w3, f.x, at.x); at.y = fmaf(w3, f.y, at.y);
            }
        }
        for (; l < cnt; l++) {
            int src = __shfl_sync(0xFFFFFFFFu, e2.x, l);
            float w = __int_as_float(__shfl_sync(0xFFFFFFFFu, e2.y, l));
            uint2 v = h64[(size_t)src * HU2 + lane];
            float2 f = __half22float2(*(const __half2*)&v.x);
            float2 g = __half22float2(*(const __half2*)&v.y);
            am.x = fmaf(w, f.x, am.x); am.y = fmaf(w, f.y, am.y);
            am.z = fmaf(w, g.x, am.z); am.w = fmaf(w, g.y, am.w);
            if (tl) {
                float2 r = __half22float2(h2[(size_t)src * H2 + 64 + lane]);
                at.x = fmaf(w, r.x, at.x); at.y = fmaf(w, r.y, at.y);
            }
        }
    }

    // epilogue: bias + ReLU + precomputed BN affine -> fp16 packed store
    const float* sc = g_sc[layer];
    const float* sh = g_sh[layer];
    {
        int d = 4 * lane;    // 0..124, all 4 cols < 128 < DIM
        float vx = fmaxf(am.x + b[d], 0.f)     * sc[d]     + sh[d];
        float vy = fmaxf(am.y + b[d + 1], 0.f) * sc[d + 1] + sh[d + 1];
        float vz = fmaxf(am.z + b[d + 2], 0.f) * sc[d + 2] + sh[d + 2];
        float vw = fmaxf(am.w + b[d + 3], 0.f) * sc[d + 3] + sh[d + 3];
        uint2 o;
        __half2 o0 = __floats2half2_rn(vx, vy);
        __half2 o1 = __floats2half2_rn(vz, vw);
        o.x = *(const unsigned*)&o0;
        o.y = *(const unsigned*)&o1;
        ((uint2*)g_t)[(size_t)node * HU2 + lane] = o;
    }
    if (tl) {
        int d = 128 + 2 * lane;                 // 128,130,132
        float vx = fmaxf(at.x + b[d], 0.f) * sc[d] + sh[d];
        float vy = 0.f;
        if (d + 1 < DIM) vy = fmaxf(at.y + b[d + 1], 0.f) * sc[d + 1] + sh[d + 1];
        ((__half2*)g_t)[(size_t)node * H2 + 64 + lane] = __floats2half2_rn(vx, vy);
    }
}

// ---------------- pooling: one warp per graph, no atomics ----------------
__global__ __launch_bounds__(256) void pool_kernel(float* __restrict__ out) {
    int g = (blockIdx.x * blockDim.x + threadIdx.x) >> 5;
    int lane = threadIdx.x & 31;
    if (g >= N_GRAPHS) return;
    int s = g_goff[g], e = g_goff[g + 1];
    const __half2* __restrict__ t2 = (const __half2*)g_t;
    float2 a0 = make_float2(0.f, 0.f);
    float2 a1 = make_float2(0.f, 0.f);
    float2 a2 = make_float2(0.f, 0.f);
    for (int n = s; n < e; n++) {
        const __half2* r = t2 + (size_t)n * H2;
        float2 p = __half22float2(r[lane]);
        float2 q = __half22float2(r[32 + lane]);
        a0.x += p.x; a0.y += p.y;
        a1.x += q.x; a1.y += q.y;
        if (lane < 3) {
            float2 rr = __half22float2(r[64 + lane]);
            a2.x += rr.x; a2.y += rr.y;
        }
    }
    float inv = 1.f / fmaxf((float)(e - s), 1.f);
    int d0 = 2 * lane;
    out[g * DIM + d0]     = a0.x * inv;
    out[g * DIM + d0 + 1] = a0.y * inv;
    out[g * DIM + 64 + d0]     = a1.x * inv;
    out[g * DIM + 64 + d0 + 1] = a1.y * inv;
    if (lane < 3) {
        int d = 128 + 2 * lane;
        out[g * DIM + d] = a2.x * inv;
        if (d + 1 < DIM) out[g * DIM + d + 1] = a2.y * inv;
    }
}

// ---------------- launch (sequential, single stream) ----------------
extern "C" void kernel_launch(void* const* d_in, const int* in_sizes, int n_in,
                              void* d_out, int out_size) {
    const float* x     = (const float*)d_in[0];
    const int*   ei    = (const int*)d_in[1];   // [2, E] int32
    const int*   batch = (const int*)d_in[2];   // [N] int32
    const float* W1 = (const float*)d_in[3];
    const float* b1 = (const float*)d_in[4];
    const float* W2 = (const float*)d_in[5];
    const float* b2 = (const float*)d_in[6];
    const float* g1 = (const float*)d_in[7];
    const float* be1 = (const float*)d_in[8];
    const float* rm1 = (const float*)d_in[9];
    const float* rv1 = (const float*)d_in[10];
    const float* g2 = (const float*)d_in[11];
    const float* be2 = (const float*)d_in[12];
    const float* rm2 = (const float*)d_in[13];
    const float* rv2 = (const float*)d_in[14];
    float* out = (float*)d_out;

    const int* row = ei;            // first E entries
    const int* col = ei + N_EDGES;  // second E entries

    const int SMEM_W = WSTRIDE * WSTRIDE * 4;   // 73984 bytes dynamic
    cudaFuncSetAttribute(gemm_tc_kernel,
                         cudaFuncAttributeMaxDynamicSharedMemorySize, SMEM_W);

    // 1. CSR build (+ per-graph ranges + BN affine precompute)
    prep_kernel<<<NB, 256>>>(batch, g1, be1, rm1, rv1, g2, be2, rm2, rv2);
    hist_kernel<<<2048, 256>>>(col);
    reduce_kernel<<<NB, 256>>>();
    scan_apply_kernel<<<NB, 256>>>();
    scatter_kernel<<<2048, 256>>>(row, col);

    // 2. layer 1: tf32 GEMM -> aggregate (+bias, ReLU, BN fused)
    gemm_tc_kernel<<<(N_NODES + 63) / 64, 128, SMEM_W>>>(x, W1, 0);
    agg_kernel<<<(N_NODES * 32 + 255) / 256, 256>>>(b1, 0);

    // 3. layer 2 (A comes from g_t, fp16)
    gemm_tc_kernel<<<(N_NODES + 63) / 64, 128, SMEM_W>>>(x, W2, 1);
    agg_kernel<<<(N_NODES * 32 + 255) / 256, 256>>>(b2, 1);

    // 4. global mean pool (sorted batch -> contiguous ranges, no atomics)
    pool_kernel<<<(N_GRAPHS * 32 + 255) / 256, 256>>>(out);
}